// round 3
// baseline (speedup 1.0000x reference)
#include <cuda_runtime.h>
#include <math.h>
#include <stdint.h>

// ---------------------------------------------------------------------------
// Problem constants
// ---------------------------------------------------------------------------
#define S_LEN   512
#define BATCH   64
#define D_IN    256
#define HID     512
#define G4      2048        // 4 gates * HID, packed unit-major: col = u*4 + gate
#define NH      4
#define DK      128
#define ROWS    (S_LEN*BATCH)        // 32768
#define DEC_ELEMS (S_LEN*BATCH*HID)  // 16777216
#define NB      128                  // persistent LSTM blocks
#define HPAD    516                  // padded h row (4*odd -> conflict-free)
#define WS_FLOATS (HID*16)           // 8192 floats weight slice

// ---------------------------------------------------------------------------
// Device scratch (static allocations only — no cudaMalloc allowed)
// ---------------------------------------------------------------------------
__device__ float g_Wxp[D_IN*G4];          //   2 MB  packed input-gate weights
__device__ float g_Whp[HID*G4];           //   4 MB  packed recurrent-gate weights
__device__ float g_biasp[G4];
__device__ float g_gx[ROWS*G4];           // 256 MB  x-side gate preacts; reused as attn scores
__device__ float g_lstm[ROWS*HID];        //  64 MB  lstm_out [S,B,HID] flattened
__device__ float g_h[2][BATCH*HID];       //  h double buffer
__device__ float g_c[BATCH*HID];
__device__ float g_PQ[ROWS*HID];          //  64 MB
__device__ float g_PK[ROWS*HID];
__device__ float g_PV[ROWS*HID];
__device__ unsigned g_cnt;                //  grid barrier counter

// ---------------------------------------------------------------------------
// PTX helpers
// ---------------------------------------------------------------------------
#define FMA2(d, a, b, c) \
    asm("fma.rn.f32x2 %0, %1, %2, %3;" : "=l"(d) : "l"(a), "l"(b), "l"(c))

__device__ __forceinline__ float sigmoid_fast(float x) {
    return 1.0f / (1.0f + __expf(-x));
}
__device__ __forceinline__ float tanh_fast2(float x) {
    // tanh(x) = 1 - 2/(exp(2x)+1); saturates correctly at +-inf
    return 1.0f - 2.0f / (__expf(2.0f * x) + 1.0f);
}

// ---------------------------------------------------------------------------
// Weight repack: gates (f,i,g,o) interleaved per hid-unit, split x-rows/h-rows
// ---------------------------------------------------------------------------
__global__ void pack_weights(const float* __restrict__ Wf, const float* __restrict__ Wi,
                             const float* __restrict__ Wg, const float* __restrict__ Wo,
                             const float* __restrict__ bf, const float* __restrict__ bi,
                             const float* __restrict__ bg, const float* __restrict__ bo)
{
    int idx = blockIdx.x * blockDim.x + threadIdx.x;   // over 768*512
    if (idx < 768*HID) {
        int k = idx / HID, u = idx % HID;
        float vf = Wf[idx], vi = Wi[idx], vg = Wg[idx], vo = Wo[idx];
        float* dst = (k < D_IN) ? (g_Wxp + (long)k*G4) : (g_Whp + (long)(k - D_IN)*G4);
        dst[u*4+0] = vf; dst[u*4+1] = vi; dst[u*4+2] = vg; dst[u*4+3] = vo;
    }
    if (idx < HID) {
        g_biasp[idx*4+0] = bf[idx];
        g_biasp[idx*4+1] = bi[idx];
        g_biasp[idx*4+2] = bg[idx];
        g_biasp[idx*4+3] = bo[idx];
    }
}

__global__ void zero_state()
{
    int i = blockIdx.x * blockDim.x + threadIdx.x;
    if (i < BATCH*HID) g_h[0][i] = 0.f;
    if (i == 0) g_cnt = 0u;
}

// ---------------------------------------------------------------------------
// Generic fp32 GEMM: C = alpha*A@B (+bias). 64x64 tile, 256 thr, 4x4 rtile.
// ---------------------------------------------------------------------------
__global__ __launch_bounds__(256)
void gemm_nn(const float* __restrict__ A, int lda, long as1, long as2,
             const float* __restrict__ B, int ldb, long bs1, long bs2,
             const float* __restrict__ bias,
             float* __restrict__ C, int ldc, long cs1, long cs2,
             int K, float alpha)
{
    int z = blockIdx.z;
    A += (long)(z >> 2) * as1 + (long)(z & 3) * as2;
    B += (long)(z >> 2) * bs1 + (long)(z & 3) * bs2;
    C += (long)(z >> 2) * cs1 + (long)(z & 3) * cs2;
    int m0 = blockIdx.y * 64, n0 = blockIdx.x * 64;

    __shared__ float As[16][68];
    __shared__ float Bs[16][68];
    int tid = threadIdx.x;
    int ty = tid >> 4, tx = tid & 15;
    float acc[4][4] = {};

    for (int k0 = 0; k0 < K; k0 += 16) {
        {
            int r = tid >> 2, c4 = tid & 3;
            float4 a = *(const float4*)(A + (long)(m0 + r) * lda + k0 + c4 * 4);
            As[c4*4+0][r] = a.x; As[c4*4+1][r] = a.y;
            As[c4*4+2][r] = a.z; As[c4*4+3][r] = a.w;
            int kk = tid >> 4, cc4 = tid & 15;
            float4 b = *(const float4*)(B + (long)(k0 + kk) * ldb + n0 + cc4 * 4);
            *(float4*)(&Bs[kk][cc4*4]) = b;
        }
        __syncthreads();
        #pragma unroll
        for (int kk = 0; kk < 16; kk++) {
            float4 av = *(const float4*)(&As[kk][ty*4]);
            float4 bv = *(const float4*)(&Bs[kk][tx*4]);
            float a_[4] = {av.x, av.y, av.z, av.w};
            float b_[4] = {bv.x, bv.y, bv.z, bv.w};
            #pragma unroll
            for (int i = 0; i < 4; i++)
                #pragma unroll
                for (int j = 0; j < 4; j++)
                    acc[i][j] += a_[i] * b_[j];
        }
        __syncthreads();
    }
    #pragma unroll
    for (int i = 0; i < 4; i++) {
        long m = m0 + ty*4 + i;
        #pragma unroll
        for (int j = 0; j < 4; j++) {
            int n = n0 + tx*4 + j;
            float v = alpha * acc[i][j];
            if (bias) v += bias[n];
            C[m * ldc + n] = v;
        }
    }
}

// C = alpha * A @ B^T   where B is [N,K] row-major (for Q@K^T)
__global__ __launch_bounds__(256)
void gemm_nt(const float* __restrict__ A, int lda, long as1, long as2,
             const float* __restrict__ B, int ldb, long bs1, long bs2,
             float* __restrict__ C, int ldc, long cs1, long cs2,
             int K, float alpha)
{
    int z = blockIdx.z;
    A += (long)(z >> 2) * as1 + (long)(z & 3) * as2;
    B += (long)(z >> 2) * bs1 + (long)(z & 3) * bs2;
    C += (long)(z >> 2) * cs1 + (long)(z & 3) * cs2;
    int m0 = blockIdx.y * 64, n0 = blockIdx.x * 64;

    __shared__ float As[16][68];
    __shared__ float Bs[16][68];
    int tid = threadIdx.x;
    int ty = tid >> 4, tx = tid & 15;
    float acc[4][4] = {};

    for (int k0 = 0; k0 < K; k0 += 16) {
        {
            int r = tid >> 2, c4 = tid & 3;
            float4 a = *(const float4*)(A + (long)(m0 + r) * lda + k0 + c4 * 4);
            As[c4*4+0][r] = a.x; As[c4*4+1][r] = a.y;
            As[c4*4+2][r] = a.z; As[c4*4+3][r] = a.w;
            float4 b = *(const float4*)(B + (long)(n0 + r) * ldb + k0 + c4 * 4);
            Bs[c4*4+0][r] = b.x; Bs[c4*4+1][r] = b.y;
            Bs[c4*4+2][r] = b.z; Bs[c4*4+3][r] = b.w;
        }
        __syncthreads();
        #pragma unroll
        for (int kk = 0; kk < 16; kk++) {
            float4 av = *(const float4*)(&As[kk][ty*4]);
            float4 bv = *(const float4*)(&Bs[kk][tx*4]);
            float a_[4] = {av.x, av.y, av.z, av.w};
            float b_[4] = {bv.x, bv.y, bv.z, bv.w};
            #pragma unroll
            for (int i = 0; i < 4; i++)
                #pragma unroll
                for (int j = 0; j < 4; j++)
                    acc[i][j] += a_[i] * b_[j];
        }
        __syncthreads();
    }
    #pragma unroll
    for (int i = 0; i < 4; i++) {
        long m = m0 + ty*4 + i;
        #pragma unroll
        for (int j = 0; j < 4; j++)
            C[m * ldc + n0 + tx*4 + j] = alpha * acc[i][j];
    }
}

// ---------------------------------------------------------------------------
// Persistent LSTM recurrence. Grid = NB=128 blocks, 512 threads.
// Block bid owns hid-units [bid*4, bid*4+4) (packed cols [bid*16, bid*16+16)).
// Thread tid = b*8 + cq*2 + gh: batch row b, unit bid*4+cq, gate-pair gh
// (gh=0 -> f,i ; gh=1 -> g,o). fma.rn.f32x2 over k-pairs; partner exchange
// via shfl.xor lane 1; grid barrier = bar + red.release / ld.acquire.
// SMEM: ws (32KB, layout [(k>>2)*64 + j*4 + (k&3)], j=cq*4+gate) then
//       hs (64 x HPAD floats), staged per step via cp.async in 2 halves.
// ---------------------------------------------------------------------------
__global__ __launch_bounds__(512)
void lstm_persistent(const float* __restrict__ gx)
{
    extern __shared__ float sm[];
    float* ws = sm;                     // 8192 floats
    float* hs = sm + WS_FLOATS;         // 64*HPAD floats

    const int tid = threadIdx.x, bid = blockIdx.x;
    const int c0  = bid * 16;
    const int b   = tid >> 3;
    const int cq  = (tid >> 1) & 3;
    const int gh  = tid & 1;
    const int u   = bid*4 + cq;

    const uint32_t smem_u32 = (uint32_t)__cvta_generic_to_shared(sm);
    const uint32_t hs_u32   = smem_u32 + WS_FLOATS * 4;

    // ---- preload + repack weight slice: ws[(k>>2)*64 + j*4 + (k&3)] ----
    for (int idx = tid; idx < WS_FLOATS; idx += 512) {
        int k = idx >> 4, j = idx & 15;
        ws[(k >> 2)*64 + j*4 + (k & 3)] = g_Whp[(long)k*G4 + c0 + j];
    }

    float creg = 0.f;
    float* h0 = g_h[0];
    float* h1 = g_h[1];
    unsigned* cnt_p = &g_cnt;

    __syncthreads();

    const uint32_t hrow_u32 = hs_u32 + (b*HPAD) * 4;
    const uint32_t wthr_u32 = smem_u32 + (cq*16 + gh*8) * 4;

    for (int t = 0; t < S_LEN; t++) {
        // prefetch this thread's gx pair (immutable input; hides DRAM latency)
        const float2 gv = *(const float2*)(gx + ((long)t*BATCH + b)*G4 + c0 + cq*4 + gh*2);

        // ---- grid barrier: wait for all blocks to finish step t-1 ----
        if (t) {
            if (tid == 0) {
                unsigned target = (unsigned)t * NB, v;
                do {
                    asm volatile("ld.acquire.gpu.global.u32 %0, [%1];"
                                 : "=r"(v) : "l"(cnt_p) : "memory");
                } while (v < target);
            }
            __syncthreads();
        }

        // ---- stage h_prev via cp.async, two halves (double-buffered) ----
        const float* hr = (t & 1) ? h1 : h0;
        #pragma unroll
        for (int half = 0; half < 2; half++) {
            #pragma unroll
            for (int i = 0; i < 8; i++) {
                int lin = tid + i*512;                 // 0..4095
                int r = lin >> 6, c4 = lin & 63;
                const float* src = hr + r*HID + half*256 + c4*4;
                uint32_t dst = hs_u32 + (r*HPAD + half*256 + c4*4) * 4;
                asm volatile("cp.async.cg.shared.global [%0], [%1], 16;"
                             :: "r"(dst), "l"(src));
            }
            asm volatile("cp.async.commit_group;");
        }

        unsigned long long acc0 = 0ULL, acc1 = 0ULL;

        asm volatile("cp.async.wait_group 1;" ::: "memory");
        __syncthreads();
        #pragma unroll 8
        for (int k = 0; k < 256; k += 4) {
            unsigned long long h01, h23, wa01, wa23, wb01, wb23;
            asm("ld.shared.v2.u64 {%0,%1}, [%2];"
                : "=l"(h01), "=l"(h23) : "r"(hrow_u32 + k*4));
            uint32_t wa = wthr_u32 + (k >> 2) * 256;   // (k/4)*64 floats
            asm("ld.shared.v2.u64 {%0,%1}, [%2];"
                : "=l"(wa01), "=l"(wa23) : "r"(wa));
            asm("ld.shared.v2.u64 {%0,%1}, [%2];"
                : "=l"(wb01), "=l"(wb23) : "r"(wa + 16));
            FMA2(acc0, h01, wa01, acc0);
            FMA2(acc0, h23, wa23, acc0);
            FMA2(acc1, h01, wb01, acc1);
            FMA2(acc1, h23, wb23, acc1);
        }
        asm volatile("cp.async.wait_group 0;" ::: "memory");
        __syncthreads();
        #pragma unroll 8
        for (int k = 256; k < 512; k += 4) {
            unsigned long long h01, h23, wa01, wa23, wb01, wb23;
            asm("ld.shared.v2.u64 {%0,%1}, [%2];"
                : "=l"(h01), "=l"(h23) : "r"(hrow_u32 + k*4));
            uint32_t wa = wthr_u32 + (k >> 2) * 256;
            asm("ld.shared.v2.u64 {%0,%1}, [%2];"
                : "=l"(wa01), "=l"(wa23) : "r"(wa));
            asm("ld.shared.v2.u64 {%0,%1}, [%2];"
                : "=l"(wb01), "=l"(wb23) : "r"(wa + 16));
            FMA2(acc0, h01, wa01, acc0);
            FMA2(acc0, h23, wa23, acc0);
            FMA2(acc1, h01, wb01, acc1);
            FMA2(acc1, h23, wb23, acc1);
        }

        // ---- horizontal sums + activations ----
        float a0x, a0y, a1x, a1y;
        asm("mov.b64 {%0,%1}, %2;" : "=f"(a0x), "=f"(a0y) : "l"(acc0));
        asm("mov.b64 {%0,%1}, %2;" : "=f"(a1x), "=f"(a1y) : "l"(acc1));
        float p0 = a0x + a0y + gv.x;   // gh0: f-pre ; gh1: g-pre
        float p1 = a1x + a1y + gv.y;   // gh0: i-pre ; gh1: o-pre
        float act0 = gh ? tanh_fast2(p0) : sigmoid_fast(p0);
        float act1 = sigmoid_fast(p1);
        float q0 = __shfl_xor_sync(0xFFFFFFFFu, act0, 1);
        float q1 = __shfl_xor_sync(0xFFFFFFFFu, act1, 1);

        if (!gh) {
            float f = act0, ii = act1, gg = q0, o = q1;
            creg = f * creg + ii * gg;
            float hn = o * tanh_fast2(creg);
            float* hw = (t & 1) ? h0 : h1;
            hw[b*HID + u] = hn;
            g_lstm[((long)t*BATCH + b)*HID + u] = hn;
            if (t == S_LEN-1) g_c[b*HID + u] = creg;
        }

        // ---- arrive: cta barrier then one release-atomic ----
        __syncthreads();
        if (tid == 0) {
            asm volatile("red.release.gpu.global.add.u32 [%0], %1;"
                         :: "l"(cnt_p), "r"(1u) : "memory");
        }
    }
}

// ---------------------------------------------------------------------------
// Row softmax over 512-wide rows. One block (128 threads) per row.
// ---------------------------------------------------------------------------
__global__ __launch_bounds__(128)
void softmax512(float* __restrict__ s)
{
    float* row = s + (size_t)blockIdx.x * 512;
    int tid = threadIdx.x;
    float v0 = row[tid], v1 = row[tid+128], v2 = row[tid+256], v3 = row[tid+384];
    float mx = fmaxf(fmaxf(v0, v1), fmaxf(v2, v3));
    __shared__ float sm[4];
    __shared__ float ss[4];
    #pragma unroll
    for (int off = 16; off > 0; off >>= 1)
        mx = fmaxf(mx, __shfl_xor_sync(0xFFFFFFFFu, mx, off));
    if ((tid & 31) == 0) sm[tid >> 5] = mx;
    __syncthreads();
    mx = fmaxf(fmaxf(sm[0], sm[1]), fmaxf(sm[2], sm[3]));
    v0 = expf(v0 - mx); v1 = expf(v1 - mx); v2 = expf(v2 - mx); v3 = expf(v3 - mx);
    float sum = v0 + v1 + v2 + v3;
    #pragma unroll
    for (int off = 16; off > 0; off >>= 1)
        sum += __shfl_xor_sync(0xFFFFFFFFu, sum, off);
    if ((tid & 31) == 0) ss[tid >> 5] = sum;
    __syncthreads();
    sum = ss[0] + ss[1] + ss[2] + ss[3];
    float inv = 1.f / sum;
    row[tid] = v0*inv; row[tid+128] = v1*inv; row[tid+256] = v2*inv; row[tid+384] = v3*inv;
}

__global__ void copy_hc(const float* __restrict__ h, const float* __restrict__ c,
                        float* __restrict__ out)
{
    int i = blockIdx.x * blockDim.x + threadIdx.x;
    if (i < BATCH*HID) {
        out[DEC_ELEMS + i] = h[i];
        out[DEC_ELEMS + BATCH*HID + i] = c[i];
    }
}

// ---------------------------------------------------------------------------
// Host orchestration (graph-capturable: launches only)
// ---------------------------------------------------------------------------
extern "C" void kernel_launch(void* const* d_in, const int* in_sizes, int n_in,
                              void* d_out, int out_size)
{
    const float* x  = (const float*)d_in[0];
    const float* Wf = (const float*)d_in[1];
    const float* bf = (const float*)d_in[2];
    const float* Wi = (const float*)d_in[3];
    const float* bi = (const float*)d_in[4];
    const float* Wg = (const float*)d_in[5];
    const float* bg = (const float*)d_in[6];
    const float* Wo = (const float*)d_in[7];
    const float* bo = (const float*)d_in[8];
    const float* Wq = (const float*)d_in[9];
    const float* bq = (const float*)d_in[10];
    const float* Wk = (const float*)d_in[11];
    const float* bk = (const float*)d_in[12];
    const float* Wv = (const float*)d_in[13];
    const float* bv = (const float*)d_in[14];
    float* out = (float*)d_out;

    float *Wxp, *biasp, *gx, *lstm, *hbase, *c, *PQ, *PK, *PV;
    cudaGetSymbolAddress((void**)&Wxp,   g_Wxp);
    cudaGetSymbolAddress((void**)&biasp, g_biasp);
    cudaGetSymbolAddress((void**)&gx,    g_gx);
    cudaGetSymbolAddress((void**)&lstm,  g_lstm);
    cudaGetSymbolAddress((void**)&hbase, g_h);
    cudaGetSymbolAddress((void**)&c,     g_c);
    cudaGetSymbolAddress((void**)&PQ,    g_PQ);
    cudaGetSymbolAddress((void**)&PK,    g_PK);
    cudaGetSymbolAddress((void**)&PV,    g_PV);
    float* h0 = hbase;

    const int SMEM_LSTM = (WS_FLOATS + BATCH*HPAD) * (int)sizeof(float);  // 164,864 B
    static int smem_set = 0;
    if (!smem_set) {
        cudaFuncSetAttribute(lstm_persistent,
                             cudaFuncAttributeMaxDynamicSharedMemorySize, SMEM_LSTM);
        smem_set = 1;
    }

    // 1. repack weights + zero h0/barrier counter
    pack_weights<<<(768*HID + 255)/256, 256>>>(Wf, Wi, Wg, Wo, bf, bi, bg, bo);
    zero_state<<<(BATCH*HID + 255)/256, 256>>>();

    // 2. x-side gate preacts: gx = x @ Wxp + biasp   [32768,256]@[256,2048]
    gemm_nn<<<dim3(G4/64, ROWS/64, 1), 256>>>(
        x, D_IN, 0, 0, Wxp, G4, 0, 0, biasp, gx, G4, 0, 0, D_IN, 1.0f);

    // 3. recurrence: single persistent kernel, device grid barrier per step
    lstm_persistent<<<NB, 512, SMEM_LSTM>>>(gx);

    // 4. Q/K/V projections: [32768,512]@[512,512]+b
    gemm_nn<<<dim3(HID/64, ROWS/64, 1), 256>>>(
        lstm, HID, 0, 0, Wq, HID, 0, 0, bq, PQ, HID, 0, 0, HID, 1.0f);
    gemm_nn<<<dim3(HID/64, ROWS/64, 1), 256>>>(
        lstm, HID, 0, 0, Wk, HID, 0, 0, bk, PK, HID, 0, 0, HID, 1.0f);
    gemm_nn<<<dim3(HID/64, ROWS/64, 1), 256>>>(
        lstm, HID, 0, 0, Wv, HID, 0, 0, bv, PV, HID, 0, 0, HID, 1.0f);

    // 5. scores = (Q @ K^T)/sqrt(dk), z = b'*4 + h
    const long pbS = (long)S_LEN * HID;
    const long phS = DK;
    const long scB = 4L * S_LEN * S_LEN;
    const long scH = (long)S_LEN * S_LEN;
    float scale = 1.0f / sqrtf((float)DK);
    gemm_nt<<<dim3(S_LEN/64, S_LEN/64, BATCH*NH), 256>>>(
        PQ, HID, pbS, phS,
        PK, HID, pbS, phS,
        gx /* reused as scores */, S_LEN, scB, scH, DK, scale);

    // 6. softmax over last axis
    softmax512<<<BATCH*NH*S_LEN, 128>>>(gx);

    // 7. out = attn @ V, written directly in decoded layout
    gemm_nn<<<dim3(DK/64, S_LEN/64, BATCH*NH), 256>>>(
        gx, S_LEN, scB, scH,
        PV, HID, pbS, phS,
        (const float*)0,
        out, BATCH*HID, (long)HID, (long)DK,
        S_LEN, 1.0f);

    // 8. final hidden/cell state (after step 511 the live h buffer is h0)
    copy_hc<<<(BATCH*HID + 255)/256, 256>>>(h0, c, out);
}